// round 1
// baseline (speedup 1.0000x reference)
#include <cuda_runtime.h>
#include <cuda_bf16.h>
#include <math.h>

// ---------------- constants ----------------
#define B_   8
#define C_   768
#define H_   32
#define W_   32
#define T_   1024          // H*W
#define L_   2
#define FF_  3072
#define NPTS 2048          // PH*PW*K
#define TOPK_ 5
#define AROUND_ 5
#define NHEAD_ 8
#define HD_  96

// ---------------- scratch (device globals; allocation-free) ----------------
__device__ float g_pf    [(size_t)B_*NPTS*C_];
__device__ float g_hid   [(size_t)B_*NPTS*C_];
__device__ float g_coords[(size_t)B_*NPTS*2];
__device__ float g_score [(size_t)B_*NPTS];
__device__ int   g_topidx[B_*TOPK_];
__device__ float g_mem   [(size_t)B_*10*C_];
__device__ float g_tgt   [(size_t)B_*T_*C_];
__device__ float g_tmp   [(size_t)B_*T_*C_];
__device__ float g_qkv   [(size_t)B_*T_*3*C_];
__device__ float g_S     [(size_t)B_*NHEAD_*T_*T_];   // 256 MB
__device__ float g_attn  [(size_t)B_*T_*C_];
__device__ float g_ffh   [(size_t)B_*T_*FF_];
__device__ float g_memkv [(size_t)B_*10*2*C_];
__device__ float g_q     [(size_t)B_*T_*C_];

// ---------------- bilinear helpers (grid_sample, zeros pad, align_corners=False) --
__device__ __forceinline__ float bilin_img(const float* __restrict__ img, float ix, float iy){
    float x0f = floorf(ix), y0f = floorf(iy);
    int x0 = (int)x0f, y0 = (int)y0f;
    float wx1 = ix - x0f, wy1 = iy - y0f;
    float wx0 = 1.f - wx1, wy0 = 1.f - wy1;
    float v = 0.f;
    bool vx0 = (x0 >= 0) & (x0 < 32);
    bool vx1 = (x0 + 1 >= 0) & (x0 + 1 < 32);
    bool vy0 = (y0 >= 0) & (y0 < 32);
    bool vy1 = (y0 + 1 >= 0) & (y0 + 1 < 32);
    if (vx0 & vy0) v += img[y0*32 + x0]         * wx0 * wy0;
    if (vx1 & vy0) v += img[y0*32 + x0 + 1]     * wx1 * wy0;
    if (vx0 & vy1) v += img[(y0+1)*32 + x0]     * wx0 * wy1;
    if (vx1 & vy1) v += img[(y0+1)*32 + x0 + 1] * wx1 * wy1;
    return v;
}
__device__ __forceinline__ float bilin_pe(const float* __restrict__ pe, float ix, float iy, int c){
    float x0f = floorf(ix), y0f = floorf(iy);
    int x0 = (int)x0f, y0 = (int)y0f;
    float wx1 = ix - x0f, wy1 = iy - y0f;
    float wx0 = 1.f - wx1, wy0 = 1.f - wy1;
    float v = 0.f;
    bool vx0 = (x0 >= 0) & (x0 < 32);
    bool vx1 = (x0 + 1 >= 0) & (x0 + 1 < 32);
    bool vy0 = (y0 >= 0) & (y0 < 32);
    bool vy1 = (y0 + 1 >= 0) & (y0 + 1 < 32);
    if (vx0 & vy0) v += pe[((size_t)(y0*32 + x0))*C_ + c]         * wx0 * wy0;
    if (vx1 & vy0) v += pe[((size_t)(y0*32 + x0 + 1))*C_ + c]     * wx1 * wy0;
    if (vx0 & vy1) v += pe[((size_t)((y0+1)*32 + x0))*C_ + c]     * wx0 * wy1;
    if (vx1 & vy1) v += pe[((size_t)((y0+1)*32 + x0 + 1))*C_ + c] * wx1 * wy1;
    return v;
}

// ---------------- 1. blockwise sampling: coords + pf ----------------
__global__ void sample_kernel(const float* __restrict__ x, const float* __restrict__ brand,
                              float* __restrict__ pf, float* __restrict__ coords){
    int bn = blockIdx.x;                // b*2048 + n
    int b  = bn >> 11;
    int n  = bn & 2047;
    int k  = n & 1;
    int pw = (n >> 1) & 31;
    int ph = n >> 6;
    const float bs = 0.0625f;
    const float* br = brand + ((((size_t)b*32 + ph)*32 + pw)*2 + k)*2;
    float gx = br[0]*bs + (-1.0f + ph*bs);
    float gy = br[1]*bs + (-1.0f + pw*bs);
    float ix = ((gx + 1.0f)*32.0f - 1.0f)*0.5f;
    float iy = ((gy + 1.0f)*32.0f - 1.0f)*0.5f;
    if (threadIdx.x == 0){ coords[(size_t)bn*2] = gx; coords[(size_t)bn*2 + 1] = gy; }
    for (int c = threadIdx.x; c < C_; c += blockDim.x){
        const float* img = x + ((size_t)b*C_ + c)*T_;
        pf[(size_t)bn*C_ + c] = bilin_img(img, ix, iy);
    }
}

// ---------------- 2. generic SGEMM: C = A@B + bias (opt relu) ----------------
template<bool RELU>
__global__ __launch_bounds__(256)
void sgemm_kernel(const float* __restrict__ A, const float* __restrict__ B,
                  const float* __restrict__ bias, float* __restrict__ C,
                  int M, int N, int K, int lda, int ldb, int ldc){
    __shared__ float As[8][128];
    __shared__ float Bs[8][128];
    int tid = threadIdx.x;
    int row0 = blockIdx.y * 128;
    int col0 = blockIdx.x * 128;
    int tx = tid & 15, ty = tid >> 4;
    float acc[8][8];
    #pragma unroll
    for (int i = 0; i < 8; i++)
        #pragma unroll
        for (int j = 0; j < 8; j++) acc[i][j] = 0.f;

    int aRow = tid >> 1;
    int aCol = (tid & 1) * 4;
    int bRow = tid >> 5;
    int bCol = (tid & 31) * 4;

    for (int k0 = 0; k0 < K; k0 += 8){
        float4 av = make_float4(0.f,0.f,0.f,0.f);
        if (row0 + aRow < M)
            av = *(const float4*)(A + (size_t)(row0 + aRow)*lda + k0 + aCol);
        As[aCol+0][aRow] = av.x; As[aCol+1][aRow] = av.y;
        As[aCol+2][aRow] = av.z; As[aCol+3][aRow] = av.w;
        float4 bv = make_float4(0.f,0.f,0.f,0.f);
        if (col0 + bCol < N)
            bv = *(const float4*)(B + (size_t)(k0 + bRow)*ldb + col0 + bCol);
        *(float4*)&Bs[bRow][bCol] = bv;
        __syncthreads();
        #pragma unroll
        for (int kk = 0; kk < 8; kk++){
            float ar[8], br[8];
            #pragma unroll
            for (int i = 0; i < 8; i++) ar[i] = As[kk][ty*8 + i];
            #pragma unroll
            for (int j = 0; j < 8; j++) br[j] = Bs[kk][tx*8 + j];
            #pragma unroll
            for (int i = 0; i < 8; i++)
                #pragma unroll
                for (int j = 0; j < 8; j++)
                    acc[i][j] += ar[i] * br[j];
        }
        __syncthreads();
    }
    #pragma unroll
    for (int i = 0; i < 8; i++){
        int r = row0 + ty*8 + i;
        if (r >= M) continue;
        #pragma unroll
        for (int j = 0; j < 8; j += 4){
            int c = col0 + tx*8 + j;
            if (c >= N) continue;
            float4 o;
            o.x = acc[i][j+0] + (bias ? bias[c+0] : 0.f);
            o.y = acc[i][j+1] + (bias ? bias[c+1] : 0.f);
            o.z = acc[i][j+2] + (bias ? bias[c+2] : 0.f);
            o.w = acc[i][j+3] + (bias ? bias[c+3] : 0.f);
            if (RELU){
                o.x = fmaxf(o.x, 0.f); o.y = fmaxf(o.y, 0.f);
                o.z = fmaxf(o.z, 0.f); o.w = fmaxf(o.w, 0.f);
            }
            *(float4*)(C + (size_t)r*ldc + c) = o;
        }
    }
}

static void gemm(const float* A, const float* B, const float* bias, float* C,
                 int M, int N, int K, int lda, int ldb, int ldc, bool relu){
    dim3 grid((N + 127)/128, (M + 127)/128);
    if (relu) sgemm_kernel<true ><<<grid, 256>>>(A, B, bias, C, M, N, K, lda, ldb, ldc);
    else      sgemm_kernel<false><<<grid, 256>>>(A, B, bias, C, M, N, K, lda, ldb, ldc);
}

// ---------------- 3. score = hid . w2 + b2 ----------------
__global__ void score_kernel(const float* __restrict__ hid, const float* __restrict__ w2,
                             const float* __restrict__ b2, float* __restrict__ score){
    int row = blockIdx.x;
    float p = 0.f;
    for (int c = threadIdx.x; c < C_; c += 256) p += hid[(size_t)row*C_ + c] * w2[c];
    #pragma unroll
    for (int o = 16; o; o >>= 1) p += __shfl_down_sync(0xffffffffu, p, o);
    __shared__ float red[8];
    if ((threadIdx.x & 31) == 0) red[threadIdx.x >> 5] = p;
    __syncthreads();
    if (threadIdx.x == 0){
        float s = 0.f;
        #pragma unroll
        for (int i = 0; i < 8; i++) s += red[i];
        score[row] = s + b2[0];
    }
}

// ---------------- 4. top-5 per batch ----------------
__global__ void topk_kernel(const float* __restrict__ score, int* __restrict__ topidx){
    int b = blockIdx.x;
    __shared__ float sv[2048];
    __shared__ float rv[256];
    __shared__ int   ri[256];
    for (int j = threadIdx.x; j < 2048; j += 256) sv[j] = score[(size_t)b*2048 + j];
    __syncthreads();
    for (int t = 0; t < TOPK_; t++){
        float bv = -1e30f; int bi = 0x7fffffff;
        for (int j = threadIdx.x; j < 2048; j += 256){
            float v = sv[j];
            if (v > bv){ bv = v; bi = j; }
        }
        rv[threadIdx.x] = bv; ri[threadIdx.x] = bi;
        __syncthreads();
        for (int s = 128; s; s >>= 1){
            if (threadIdx.x < s){
                float v2 = rv[threadIdx.x + s]; int i2 = ri[threadIdx.x + s];
                if (v2 > rv[threadIdx.x] || (v2 == rv[threadIdx.x] && i2 < ri[threadIdx.x])){
                    rv[threadIdx.x] = v2; ri[threadIdx.x] = i2;
                }
            }
            __syncthreads();
        }
        if (threadIdx.x == 0){
            topidx[b*TOPK_ + t] = ri[0];
            sv[ri[0]] = -1e30f;
        }
        __syncthreads();
    }
}

// ---------------- 5. soft_align + modality query -> mem rows ----------------
__global__ void soft_align_kernel(const float* __restrict__ mainx, const float* __restrict__ pe,
                                  const float* __restrict__ arand, const float* __restrict__ mqrow,
                                  const float* __restrict__ pf, const float* __restrict__ coords,
                                  const int* __restrict__ topidx, float* __restrict__ memo, int rowBase){
    int b  = blockIdx.x / TOPK_;
    int nk = blockIdx.x % TOPK_;
    int idx = topidx[b*TOPK_ + nk];
    float px = coords[((size_t)b*NPTS + idx)*2 + 0];
    float py = coords[((size_t)b*NPTS + idx)*2 + 1];
    __shared__ float semb[AROUND_*C_];
    __shared__ float red[256];
    __shared__ float res[11];
    __shared__ float sw[AROUND_];
    float ixs[AROUND_], iys[AROUND_];
    #pragma unroll
    for (int a = 0; a < AROUND_; a++){
        const float* ar = arand + (((size_t)b*AROUND_ + a)*TOPK_ + nk)*2;
        float g0 = px + (ar[0]*2.f - 0.5f)*0.2f;
        float g1 = py + (ar[1]*2.f - 0.5f)*0.2f;
        g0 = fminf(fmaxf(g0, -1.f), 1.f);
        g1 = fminf(fmaxf(g1, -1.f), 1.f);
        ixs[a] = ((g0 + 1.f)*32.f - 1.f)*0.5f;
        iys[a] = ((g1 + 1.f)*32.f - 1.f)*0.5f;
    }
    const float* pfrow = pf + ((size_t)b*NPTS + idx)*C_;
    float rep2 = 0.f, num[AROUND_], af2[AROUND_];
    #pragma unroll
    for (int a = 0; a < AROUND_; a++){ num[a] = 0.f; af2[a] = 0.f; }
    for (int c = threadIdx.x; c < C_; c += 256){
        float r = pfrow[c];
        rep2 += r*r;
        const float* img = mainx + ((size_t)b*C_ + c)*T_;
        #pragma unroll
        for (int a = 0; a < AROUND_; a++){
            float af = bilin_img(img, ixs[a], iys[a]);
            num[a] += r*af;
            af2[a] += af*af;
            semb[a*C_ + c] = bilin_pe(pe, ixs[a], iys[a], c);
        }
    }
    float vals[11];
    vals[0] = rep2;
    #pragma unroll
    for (int a = 0; a < AROUND_; a++){ vals[1+a] = num[a]; vals[6+a] = af2[a]; }
    for (int v = 0; v < 11; v++){
        red[threadIdx.x] = vals[v];
        __syncthreads();
        for (int s = 128; s; s >>= 1){
            if (threadIdx.x < s) red[threadIdx.x] += red[threadIdx.x + s];
            __syncthreads();
        }
        if (threadIdx.x == 0) res[v] = red[0];
        __syncthreads();
    }
    if (threadIdx.x == 0){
        float rn = fmaxf(sqrtf(res[0]), 1e-8f);
        float s[AROUND_]; float mx = -1e30f;
        for (int a = 0; a < AROUND_; a++){
            s[a] = res[1+a] / (rn * fmaxf(sqrtf(res[6+a]), 1e-8f));
            mx = fmaxf(mx, s[a]);
        }
        float ss = 0.f;
        for (int a = 0; a < AROUND_; a++){ s[a] = expf(s[a] - mx); ss += s[a]; }
        for (int a = 0; a < AROUND_; a++) sw[a] = s[a] / ss;
    }
    __syncthreads();
    float w0 = sw[0], w1 = sw[1], w2 = sw[2], w3 = sw[3], w4 = sw[4];
    for (int c = threadIdx.x; c < C_; c += 256){
        float o = pfrow[c] + mqrow[c];
        o += semb[0*C_ + c]*w0 + semb[1*C_ + c]*w1 + semb[2*C_ + c]*w2
           + semb[3*C_ + c]*w3 + semb[4*C_ + c]*w4;
        memo[((size_t)b*10 + rowBase + nk)*C_ + c] = o;
    }
}

// ---------------- 6. tgt init (transpose + add pe/mq) ----------------
__global__ void tgt_init_kernel(const float* __restrict__ mainx, const float* __restrict__ mq,
                                const float* __restrict__ pe, float* __restrict__ tgt){
    __shared__ float tile[32][33];
    int c0 = blockIdx.x*32, t0 = blockIdx.y*32, b = blockIdx.z;
    for (int i = threadIdx.y; i < 32; i += 8)
        tile[i][threadIdx.x] = mainx[((size_t)b*C_ + c0 + i)*T_ + t0 + threadIdx.x];
    __syncthreads();
    for (int i = threadIdx.y; i < 32; i += 8){
        int t = t0 + i, c = c0 + threadIdx.x;
        tgt[((size_t)b*T_ + t)*C_ + c] = tile[threadIdx.x][i] + mq[c] + pe[(size_t)t*C_ + c];
    }
}

// ---------------- 7. attention scores S = scale * Q K^T ----------------
__global__ __launch_bounds__(256)
void attn_scores_kernel(const float* __restrict__ qkv, float* __restrict__ S){
    int bh = blockIdx.z, b = bh >> 3, h = bh & 7;
    int q0 = blockIdx.y * 64, k0 = blockIdx.x * 64;
    const float* qb = qkv + (size_t)b*T_*3*C_ + h*HD_;
    const float* kb = qb + C_;
    __shared__ float Qs[64][33];
    __shared__ float Ks[64][33];
    int tid = threadIdx.x, tx = tid & 15, ty = tid >> 4;
    float acc[4][4];
    #pragma unroll
    for (int i = 0; i < 4; i++)
        #pragma unroll
        for (int j = 0; j < 4; j++) acc[i][j] = 0.f;
    for (int kc = 0; kc < HD_; kc += 32){
        for (int idx = tid; idx < 2048; idx += 256){
            int r = idx >> 5, c = idx & 31;
            Qs[r][c] = qb[(size_t)(q0 + r)*(3*C_) + kc + c];
            Ks[r][c] = kb[(size_t)(k0 + r)*(3*C_) + kc + c];
        }
        __syncthreads();
        #pragma unroll
        for (int kk = 0; kk < 32; kk++){
            float a[4], bb[4];
            #pragma unroll
            for (int i = 0; i < 4; i++) a[i] = Qs[ty*4 + i][kk];
            #pragma unroll
            for (int j = 0; j < 4; j++) bb[j] = Ks[tx*4 + j][kk];
            #pragma unroll
            for (int i = 0; i < 4; i++)
                #pragma unroll
                for (int j = 0; j < 4; j++)
                    acc[i][j] += a[i]*bb[j];
        }
        __syncthreads();
    }
    const float scale = 0.10206207261596577f;  // 1/sqrt(96)
    float* Sp = S + ((size_t)bh*T_ + q0)*T_ + k0;
    #pragma unroll
    for (int i = 0; i < 4; i++){
        float4 o;
        o.x = acc[i][0]*scale; o.y = acc[i][1]*scale;
        o.z = acc[i][2]*scale; o.w = acc[i][3]*scale;
        *(float4*)&Sp[(size_t)(ty*4 + i)*T_ + tx*4] = o;
    }
}

// ---------------- 8. row softmax over 1024 ----------------
__global__ void softmax_kernel(float* __restrict__ S){
    size_t row = blockIdx.x;
    float* p = S + row*T_;
    int t = threadIdx.x;
    float v[4];
    float mx = -1e30f;
    #pragma unroll
    for (int i = 0; i < 4; i++){ v[i] = p[t + i*256]; mx = fmaxf(mx, v[i]); }
    __shared__ float red[256];
    red[t] = mx; __syncthreads();
    for (int s = 128; s; s >>= 1){
        if (t < s) red[t] = fmaxf(red[t], red[t + s]);
        __syncthreads();
    }
    mx = red[0]; __syncthreads();
    float sum = 0.f;
    #pragma unroll
    for (int i = 0; i < 4; i++){ v[i] = expf(v[i] - mx); sum += v[i]; }
    red[t] = sum; __syncthreads();
    for (int s = 128; s; s >>= 1){
        if (t < s) red[t] += red[t + s];
        __syncthreads();
    }
    float inv = 1.f / red[0];
    #pragma unroll
    for (int i = 0; i < 4; i++) p[t + i*256] = v[i]*inv;
}

// ---------------- 9. O = att @ V ----------------
__global__ __launch_bounds__(256)
void attn_av_kernel(const float* __restrict__ S, const float* __restrict__ qkv,
                    float* __restrict__ out){
    int bh = blockIdx.z, b = bh >> 3, h = bh & 7;
    int q0 = blockIdx.x * 64;
    __shared__ float Ss[64][65];
    __shared__ float Vs[64][96];
    int tid = threadIdx.x, tx = tid & 15, ty = tid >> 4;
    float acc[4][6];
    #pragma unroll
    for (int i = 0; i < 4; i++)
        #pragma unroll
        for (int j = 0; j < 6; j++) acc[i][j] = 0.f;
    const float* vb = qkv + (size_t)b*T_*3*C_ + 2*C_ + h*HD_;
    const float* Sp = S + ((size_t)bh*T_ + q0)*T_;
    for (int j0 = 0; j0 < T_; j0 += 64){
        for (int idx = tid; idx < 4096; idx += 256){
            int r = idx >> 6, c = idx & 63;
            Ss[r][c] = Sp[(size_t)r*T_ + j0 + c];
        }
        for (int idx = tid; idx < 6144; idx += 256){
            int r = idx / 96, c = idx % 96;
            Vs[r][c] = vb[(size_t)(j0 + r)*(3*C_) + c];
        }
        __syncthreads();
        #pragma unroll 16
        for (int jj = 0; jj < 64; jj++){
            float a[4], bb[6];
            #pragma unroll
            for (int i = 0; i < 4; i++) a[i] = Ss[ty*4 + i][jj];
            #pragma unroll
            for (int j = 0; j < 6; j++) bb[j] = Vs[jj][tx*6 + j];
            #pragma unroll
            for (int i = 0; i < 4; i++)
                #pragma unroll
                for (int j = 0; j < 6; j++)
                    acc[i][j] += a[i]*bb[j];
        }
        __syncthreads();
    }
    #pragma unroll
    for (int i = 0; i < 4; i++)
        #pragma unroll
        for (int j = 0; j < 6; j++)
            out[((size_t)b*T_ + q0 + ty*4 + i)*C_ + h*HD_ + tx*6 + j] = acc[i][j];
}

// ---------------- 10. cross-attention (10 keys) ----------------
__global__ void ca_attn_kernel(const float* __restrict__ q, const float* __restrict__ kv,
                               float* __restrict__ out){
    int bh = blockIdx.y, b = bh >> 3, h = bh & 7;
    int i = blockIdx.x*256 + threadIdx.x;
    __shared__ float Ks[10][96];
    __shared__ float Vsm[10][96];
    for (int idx = threadIdx.x; idx < 960; idx += 256){
        int j = idx / 96, d = idx % 96;
        Ks[j][d]  = kv[((size_t)b*10 + j)*(2*C_) + h*HD_ + d];
        Vsm[j][d] = kv[((size_t)b*10 + j)*(2*C_) + C_ + h*HD_ + d];
    }
    __syncthreads();
    const float* qr = q + ((size_t)b*T_ + i)*C_ + h*HD_;
    float s[10];
    #pragma unroll
    for (int j = 0; j < 10; j++) s[j] = 0.f;
    for (int d = 0; d < HD_; d++){
        float qd = qr[d];
        #pragma unroll
        for (int j = 0; j < 10; j++) s[j] += qd * Ks[j][d];
    }
    const float scale = 0.10206207261596577f;
    float mx = -1e30f;
    #pragma unroll
    for (int j = 0; j < 10; j++){ s[j] *= scale; mx = fmaxf(mx, s[j]); }
    float sum = 0.f;
    #pragma unroll
    for (int j = 0; j < 10; j++){ s[j] = expf(s[j] - mx); sum += s[j]; }
    float inv = 1.f / sum;
    #pragma unroll
    for (int j = 0; j < 10; j++) s[j] *= inv;
    float* orow = out + ((size_t)b*T_ + i)*C_ + h*HD_;
    for (int d = 0; d < HD_; d++){
        float o = 0.f;
        #pragma unroll
        for (int j = 0; j < 10; j++) o += s[j] * Vsm[j][d];
        orow[d] = o;
    }
}

// ---------------- 11. residual add + layernorm (in place on tgt) ----------------
__global__ void add_ln_kernel(float* __restrict__ tgt, const float* __restrict__ resid,
                              const float* __restrict__ w, const float* __restrict__ bb){
    int row = blockIdx.x, t = threadIdx.x;
    float* p = tgt + (size_t)row*C_;
    const float* r = resid + (size_t)row*C_;
    float v[3];
    float sum = 0.f;
    #pragma unroll
    for (int i = 0; i < 3; i++){ v[i] = p[t + i*256] + r[t + i*256]; sum += v[i]; }
    __shared__ float red[256];
    red[t] = sum; __syncthreads();
    for (int s = 128; s; s >>= 1){ if (t < s) red[t] += red[t + s]; __syncthreads(); }
    float m = red[0] * (1.f/768.f);
    __syncthreads();
    float s2 = 0.f;
    #pragma unroll
    for (int i = 0; i < 3; i++){ float d = v[i] - m; s2 += d*d; }
    red[t] = s2; __syncthreads();
    for (int s = 128; s; s >>= 1){ if (t < s) red[t] += red[t + s]; __syncthreads(); }
    float var = red[0] * (1.f/768.f);
    float rstd = rsqrtf(var + 1e-5f);
    #pragma unroll
    for (int i = 0; i < 3; i++){
        int c = t + i*256;
        p[c] = (v[i] - m)*rstd*w[c] + bb[c];
    }
}

// ---------------- 12. final transpose [B,T,C] -> [B,C,T] ----------------
__global__ void transpose_out_kernel(const float* __restrict__ tgt, float* __restrict__ out){
    __shared__ float tile[32][33];
    int c0 = blockIdx.x*32, t0 = blockIdx.y*32, b = blockIdx.z;
    for (int i = threadIdx.y; i < 32; i += 8)
        tile[i][threadIdx.x] = tgt[((size_t)b*T_ + t0 + i)*C_ + c0 + threadIdx.x];
    __syncthreads();
    for (int i = threadIdx.y; i < 32; i += 8)
        out[((size_t)b*C_ + c0 + i)*T_ + t0 + threadIdx.x] = tile[threadIdx.x][i];
}

// ---------------- launch ----------------
extern "C" void kernel_launch(void* const* d_in, const int* in_sizes, int n_in,
                              void* d_out, int out_size){
    const float* mainx      = (const float*)d_in[0];
    const float* others[2]  = {(const float*)d_in[1], (const float*)d_in[2]};
    const float* pe         = (const float*)d_in[3];
    const float* mq         = (const float*)d_in[4];
    const float* s_w1       = (const float*)d_in[5];
    const float* s_b1       = (const float*)d_in[6];
    const float* s_w2       = (const float*)d_in[7];
    const float* s_b2       = (const float*)d_in[8];
    const float* sa_in_w    = (const float*)d_in[9];
    const float* sa_in_b    = (const float*)d_in[10];
    const float* sa_out_w   = (const float*)d_in[11];
    const float* sa_out_b   = (const float*)d_in[12];
    const float* ca_in_w    = (const float*)d_in[13];
    const float* ca_in_b    = (const float*)d_in[14];
    const float* ca_out_w   = (const float*)d_in[15];
    const float* ca_out_b   = (const float*)d_in[16];
    const float* ff1_w      = (const float*)d_in[17];
    const float* ff1_b      = (const float*)d_in[18];
    const float* ff2_w      = (const float*)d_in[19];
    const float* ff2_b      = (const float*)d_in[20];
    const float* ln_w       = (const float*)d_in[21];
    const float* ln_b       = (const float*)d_in[22];
    const float* block_rand = (const float*)d_in[23];
    const float* around_rand= (const float*)d_in[24];
    float* out = (float*)d_out;

    float *pf, *hid, *coords, *score, *memb, *tgt, *tmp, *qkv, *Sb, *attn, *ffh, *memkv, *qb;
    int* topidx;
    cudaGetSymbolAddress((void**)&pf,     g_pf);
    cudaGetSymbolAddress((void**)&hid,    g_hid);
    cudaGetSymbolAddress((void**)&coords, g_coords);
    cudaGetSymbolAddress((void**)&score,  g_score);
    cudaGetSymbolAddress((void**)&topidx, g_topidx);
    cudaGetSymbolAddress((void**)&memb,   g_mem);
    cudaGetSymbolAddress((void**)&tgt,    g_tgt);
    cudaGetSymbolAddress((void**)&tmp,    g_tmp);
    cudaGetSymbolAddress((void**)&qkv,    g_qkv);
    cudaGetSymbolAddress((void**)&Sb,     g_S);
    cudaGetSymbolAddress((void**)&attn,   g_attn);
    cudaGetSymbolAddress((void**)&ffh,    g_ffh);
    cudaGetSymbolAddress((void**)&memkv,  g_memkv);
    cudaGetSymbolAddress((void**)&qb,     g_q);

    // ---- phase A: modalities ----
    for (int i = 0; i < 2; i++){
        sample_kernel<<<B_*NPTS, 256>>>(others[i], block_rand + (size_t)i*B_*32*32*2*2, pf, coords);
        gemm(pf, s_w1, s_b1, hid, B_*NPTS, C_, C_, C_, C_, C_, true);
        score_kernel<<<B_*NPTS, 256>>>(hid, s_w2, s_b2, score);
        topk_kernel<<<B_, 256>>>(score, topidx);
        soft_align_kernel<<<B_*TOPK_, 256>>>(mainx, pe,
                                             around_rand + (size_t)i*B_*AROUND_*TOPK_*2,
                                             mq + (size_t)(i+1)*C_,
                                             pf, coords, topidx, memb, i*TOPK_);
    }

    // ---- tgt init ----
    {
        dim3 g(C_/32, T_/32, B_); dim3 bl(32, 8);
        tgt_init_kernel<<<g, bl>>>(mainx, mq, pe, tgt);
    }

    // ---- decoder layers ----
    for (int l = 0; l < L_; l++){
        // self-attention
        gemm(tgt, sa_in_w + (size_t)l*C_*3*C_, sa_in_b + (size_t)l*3*C_, qkv,
             B_*T_, 3*C_, C_, C_, 3*C_, 3*C_, false);
        { dim3 g(16, 16, B_*NHEAD_); attn_scores_kernel<<<g, 256>>>(qkv, Sb); }
        softmax_kernel<<<B_*NHEAD_*T_, 256>>>(Sb);
        { dim3 g(16, 1, B_*NHEAD_); attn_av_kernel<<<g, 256>>>(Sb, qkv, attn); }
        gemm(attn, sa_out_w + (size_t)l*C_*C_, sa_out_b + (size_t)l*C_, tmp,
             B_*T_, C_, C_, C_, C_, C_, false);
        add_ln_kernel<<<B_*T_, 256>>>(tgt, tmp, ln_w + (size_t)(l*3+0)*C_, ln_b + (size_t)(l*3+0)*C_);

        // cross-attention
        gemm(tgt, ca_in_w + (size_t)l*C_*3*C_, ca_in_b + (size_t)l*3*C_, qb,
             B_*T_, C_, C_, C_, 3*C_, C_, false);
        gemm(memb, ca_in_w + (size_t)l*C_*3*C_ + C_, ca_in_b + (size_t)l*3*C_ + C_, memkv,
             B_*10, 2*C_, C_, C_, 3*C_, 2*C_, false);
        { dim3 g(T_/256, B_*NHEAD_); ca_attn_kernel<<<g, 256>>>(qb, memkv, attn); }
        gemm(attn, ca_out_w + (size_t)l*C_*C_, ca_out_b + (size_t)l*C_, tmp,
             B_*T_, C_, C_, C_, C_, C_, false);
        add_ln_kernel<<<B_*T_, 256>>>(tgt, tmp, ln_w + (size_t)(l*3+1)*C_, ln_b + (size_t)(l*3+1)*C_);

        // feed-forward
        gemm(tgt, ff1_w + (size_t)l*C_*FF_, ff1_b + (size_t)l*FF_, ffh,
             B_*T_, FF_, C_, C_, FF_, FF_, true);
        gemm(ffh, ff2_w + (size_t)l*FF_*C_, ff2_b + (size_t)l*C_, tmp,
             B_*T_, C_, FF_, FF_, C_, C_, false);
        add_ln_kernel<<<B_*T_, 256>>>(tgt, tmp, ln_w + (size_t)(l*3+2)*C_, ln_b + (size_t)(l*3+2)*C_);
    }

    // ---- output transpose ----
    {
        dim3 g(C_/32, T_/32, B_); dim3 bl(32, 8);
        transpose_out_kernel<<<g, bl>>>(tgt, out);
    }
}